// round 3
// baseline (speedup 1.0000x reference)
#include <cuda_runtime.h>
#include <cstdint>
#include <math_constants.h>

// Sparsemax along last dim (d = 1024). Two warps per row, 16 values/lane,
// to cut register pressure (was 58 regs -> 4 blocks/SM) and raise occupancy.
// Exact threshold via Michelot fixed-point, warm start tau0 = max(z) - 1
// (valid: tau* >= max-1). Active set at tau0 is tiny for Gaussian rows, so
// it is compacted once into shared; iterations run on the compacted set.

constexpr int D   = 1024;
constexpr int RPB = 4;                // rows per block (8 warps, 2 per row)
constexpr int TPB = RPB * 64;         // 256 threads
constexpr int HALF = D / 2;           // 512 elements per warp
constexpr int VPT = 16;               // values per lane

__global__ void __launch_bounds__(TPB)
sparsemax_kernel(const float* __restrict__ z, float* __restrict__ p, int rows) {
    __shared__ float buf[RPB][D];     // compaction buffer (capacity = D, always enough)
    __shared__ float mx[RPB][2];
    __shared__ int   cn[RPB][2];

    const int warp = threadIdx.x >> 5;
    const int lane = threadIdx.x & 31;
    const int rl   = warp >> 1;       // row within block
    const int half = warp & 1;        // which half of the row
    const int row  = blockIdx.x * RPB + rl;
    if (row >= rows) return;

    const float* zr = z + (size_t)row * D + half * HALF;
    float*       pr = p + (size_t)row * D + half * HALF;

    // ---- load 512 elems: 4 x float4 per lane, coalesced, streaming ----
    float v[VPT];
#pragma unroll
    for (int j = 0; j < 4; j++) {
        float4 t = __ldcs(reinterpret_cast<const float4*>(zr + j * 128 + lane * 4));
        v[4 * j + 0] = t.x;
        v[4 * j + 1] = t.y;
        v[4 * j + 2] = t.z;
        v[4 * j + 3] = t.w;
    }

    // ---- half-row max, publish to shared ----
    float m = v[0];
#pragma unroll
    for (int i = 1; i < VPT; i++) m = fmaxf(m, v[i]);
#pragma unroll
    for (int o = 16; o > 0; o >>= 1)
        m = fmaxf(m, __shfl_xor_sync(0xffffffffu, m, o));
    if (lane == 0) mx[rl][half] = m;
    __syncthreads();

    float tau = fmaxf(mx[rl][0], mx[rl][1]) - 1.0f;

    // ---- compact this half's active set {z > tau0} into shared ----
    const unsigned lt = (1u << lane) - 1u;
    int cnt = 0;
    float* seg = &buf[rl][half * HALF];
#pragma unroll
    for (int i = 0; i < VPT; i++) {
        bool a = v[i] > tau;
        unsigned msk = __ballot_sync(0xffffffffu, a);
        if (a) seg[cnt + __popc(msk & lt)] = v[i];
        cnt += __popc(msk);
    }
    if (lane == 0) cn[rl][half] = cnt;
    __syncthreads();

    const int c0 = cn[rl][0];
    const int c1 = cn[rl][1];
    const int ct = c0 + c1;

    // ---- Michelot fixed-point iterations on the compacted set ----
    // Both warps of the row run this redundantly (bit-identical result).
    if (ct <= 32) {
        // common case: whole active set fits one register per lane
        float x = (lane < c0) ? buf[rl][lane]
                : (lane < ct) ? buf[rl][HALF + lane - c0]
                              : -CUDART_INF_F;
#pragma unroll 1
        for (int it = 0; it < 40; it++) {
            bool a = x > tau;
            float s = a ? x : 0.0f;
            int k = __popc(__ballot_sync(0xffffffffu, a));   // k >= 1 always
#pragma unroll
            for (int o = 16; o > 0; o >>= 1)
                s += __shfl_xor_sync(0xffffffffu, s, o);
            float nt = (s - 1.0f) / (float)k;
            if (nt == tau) break;   // exact fixed point = sparsemax threshold
            tau = nt;
        }
    } else {
        // rare fallback: walk both shared segments
#pragma unroll 1
        for (int it = 0; it < 64; it++) {
            float s = 0.0f, k = 0.0f;
            for (int t = lane; t < c0; t += 32) {
                float x = buf[rl][t];
                if (x > tau) { s += x; k += 1.0f; }
            }
            for (int t = lane; t < c1; t += 32) {
                float x = buf[rl][HALF + t];
                if (x > tau) { s += x; k += 1.0f; }
            }
#pragma unroll
            for (int o = 16; o > 0; o >>= 1) {
                s += __shfl_xor_sync(0xffffffffu, s, o);
                k += __shfl_xor_sync(0xffffffffu, k, o);
            }
            float nt = (s - 1.0f) / k;
            if (nt == tau) break;
            tau = nt;
        }
    }

    // ---- write p = relu(z - tau), coalesced float4 streaming stores ----
#pragma unroll
    for (int j = 0; j < 4; j++) {
        float4 t;
        t.x = fmaxf(v[4 * j + 0] - tau, 0.0f);
        t.y = fmaxf(v[4 * j + 1] - tau, 0.0f);
        t.z = fmaxf(v[4 * j + 2] - tau, 0.0f);
        t.w = fmaxf(v[4 * j + 3] - tau, 0.0f);
        __stcs(reinterpret_cast<float4*>(pr + j * 128 + lane * 4), t);
    }
}

extern "C" void kernel_launch(void* const* d_in, const int* in_sizes, int n_in,
                              void* d_out, int out_size) {
    const float* z = (const float*)d_in[0];
    float* p = (float*)d_out;
    const int rows = in_sizes[0] / D;                  // 32768
    const int grid = (rows + RPB - 1) / RPB;           // 8192
    sparsemax_kernel<<<grid, TPB>>>(z, p, rows);
}

// round 4
// speedup vs baseline: 1.0649x; 1.0649x over previous
#include <cuda_runtime.h>
#include <cstdint>
#include <math_constants.h>

// Sparsemax along last dim (d = 1024), one warp per row, row staged in SMEM
// via cp.async (no register payload -> low regs -> 6 blocks/SM, no barriers).
// Exact threshold via Michelot fixed-point from warm start tau0 = max(z)-1
// (valid: tau* >= max-1). Active set at tau0 compacted once; iterations run
// on <=32 register-resident values in the common case.

constexpr int D   = 1024;
constexpr int WPB = 8;               // warps (rows) per block
constexpr int TPB = WPB * 32;

__global__ void __launch_bounds__(TPB)
sparsemax_kernel(const float* __restrict__ z, float* __restrict__ p, int rows) {
    __shared__ float buf[WPB][D];     // 32 KB row staging
    __shared__ float comp[WPB][32];   // compacted active set (common case)

    const int wl   = threadIdx.x >> 5;
    const int lane = threadIdx.x & 31;
    const int row  = blockIdx.x * WPB + wl;
    if (row >= rows) return;

    const float* zr = z + (size_t)row * D;
    float*       pr = p + (size_t)row * D;

    // ---- async copy row into shared: 8 x 16B per lane, L1-bypass (.cg) ----
    uint32_t sbase = (uint32_t)__cvta_generic_to_shared(&buf[wl][0]);
#pragma unroll
    for (int j = 0; j < 8; j++) {
        uint32_t saddr = sbase + (uint32_t)(j * 128 + lane * 4) * 4u;
        const float* gaddr = zr + j * 128 + lane * 4;
        asm volatile("cp.async.cg.shared.global [%0], [%1], 16;\n"
                     :: "r"(saddr), "l"(gaddr));
    }
    asm volatile("cp.async.commit_group;\n");
    asm volatile("cp.async.wait_group 0;\n" ::: "memory");
    __syncwarp();

    // ---- row max (read smem, 8 x LDS.128, conflict-free) ----
    float m = -CUDART_INF_F;
#pragma unroll
    for (int j = 0; j < 8; j++) {
        float4 t = *reinterpret_cast<const float4*>(&buf[wl][j * 128 + lane * 4]);
        m = fmaxf(m, fmaxf(fmaxf(t.x, t.y), fmaxf(t.z, t.w)));
    }
#pragma unroll
    for (int o = 16; o > 0; o >>= 1)
        m = fmaxf(m, __shfl_xor_sync(0xffffffffu, m, o));

    float tau = m - 1.0f;

    // ---- compact active set {z > tau0}; capacity 32 (overflow -> fallback) ----
    const unsigned lt = (1u << lane) - 1u;
    int cnt = 0;
#pragma unroll
    for (int j = 0; j < 8; j++) {
        float4 t = *reinterpret_cast<const float4*>(&buf[wl][j * 128 + lane * 4]);
        float vv[4] = {t.x, t.y, t.z, t.w};
#pragma unroll
        for (int q = 0; q < 4; q++) {
            bool a = vv[q] > tau;
            unsigned msk = __ballot_sync(0xffffffffu, a);
            int pos = cnt + __popc(msk & lt);
            if (a && pos < 32) comp[wl][pos] = vv[q];
            cnt += __popc(msk);
        }
    }
    __syncwarp();

    // ---- Michelot fixed-point iterations ----
    if (cnt <= 32) {
        // common case: whole active set in one register per lane
        float x = (lane < cnt) ? comp[wl][lane] : -CUDART_INF_F;
#pragma unroll 1
        for (int it = 0; it < 40; it++) {
            bool a = x > tau;
            float s = a ? x : 0.0f;
            int k = __popc(__ballot_sync(0xffffffffu, a));   // k >= 1 always
#pragma unroll
            for (int o = 16; o > 0; o >>= 1)
                s += __shfl_xor_sync(0xffffffffu, s, o);
            float nt = (s - 1.0f) / (float)k;
            if (nt == tau) break;   // exact fixed point = sparsemax threshold
            tau = nt;
        }
    } else {
        // rare fallback: iterate over the full smem row
#pragma unroll 1
        for (int it = 0; it < 64; it++) {
            float s = 0.0f, kk = 0.0f;
#pragma unroll 1
            for (int j = 0; j < 8; j++) {
                float4 t = *reinterpret_cast<const float4*>(&buf[wl][j * 128 + lane * 4]);
                if (t.x > tau) { s += t.x; kk += 1.0f; }
                if (t.y > tau) { s += t.y; kk += 1.0f; }
                if (t.z > tau) { s += t.z; kk += 1.0f; }
                if (t.w > tau) { s += t.w; kk += 1.0f; }
            }
#pragma unroll
            for (int o = 16; o > 0; o >>= 1) {
                s  += __shfl_xor_sync(0xffffffffu, s, o);
                kk += __shfl_xor_sync(0xffffffffu, kk, o);
            }
            float nt = (s - 1.0f) / kk;
            if (nt == tau) break;
            tau = nt;
        }
    }

    // ---- write p = relu(z - tau): smem read + coalesced streaming stores ----
#pragma unroll
    for (int j = 0; j < 8; j++) {
        float4 t = *reinterpret_cast<const float4*>(&buf[wl][j * 128 + lane * 4]);
        t.x = fmaxf(t.x - tau, 0.0f);
        t.y = fmaxf(t.y - tau, 0.0f);
        t.z = fmaxf(t.z - tau, 0.0f);
        t.w = fmaxf(t.w - tau, 0.0f);
        __stcs(reinterpret_cast<float4*>(pr + j * 128 + lane * 4), t);
    }
}

extern "C" void kernel_launch(void* const* d_in, const int* in_sizes, int n_in,
                              void* d_out, int out_size) {
    const float* z = (const float*)d_in[0];
    float* p = (float*)d_out;
    const int rows = in_sizes[0] / D;                  // 32768
    const int grid = (rows + WPB - 1) / WPB;           // 4096
    sparsemax_kernel<<<grid, TPB>>>(z, p, rows);
}

// round 6
// speedup vs baseline: 1.0956x; 1.0288x over previous
#include <cuda_runtime.h>
#include <cstdint>
#include <math_constants.h>

// Sparsemax along last dim (d = 1024), one warp per row, row in registers.
// Exact threshold via Michelot fixed-point warm-started at tau0 = max(z)-1
// (valid: tau* >= max-1, since sum(p)=1 forces p_max <= 1).
// Active values at tau0 (~14 of 1024 for Gaussian rows) are binned into up
// to 3 registers per lane (no smem, no serial ballot compaction); Michelot
// then iterates on those slots. Rare overflow (-> >3 actives in one lane)
// falls back to full-register iteration. No block barriers anywhere.

constexpr int D   = 1024;
constexpr int WPB = 8;               // warps (rows) per block
constexpr int TPB = WPB * 32;

// Order-preserving float<->int mapping (valid for non-NaN inputs).
__device__ __forceinline__ int f2i_mono(float f) {
    int i = __float_as_int(f);
    return i >= 0 ? i : i ^ 0x7fffffff;
}
__device__ __forceinline__ float i2f_mono(int i) {
    return __int_as_float(i >= 0 ? i : i ^ 0x7fffffff);
}

__device__ __forceinline__ float warp_sum(float x) {
#pragma unroll
    for (int o = 16; o > 0; o >>= 1)
        x += __shfl_xor_sync(0xffffffffu, x, o);
    return x;
}

__global__ void __launch_bounds__(TPB)
sparsemax_kernel(const float* __restrict__ z, float* __restrict__ p, int rows) {
    const int wl   = threadIdx.x >> 5;
    const int lane = threadIdx.x & 31;
    const int row  = blockIdx.x * WPB + wl;
    if (row >= rows) return;

    const float* zr = z + (size_t)row * D;
    float*       pr = p + (size_t)row * D;

    // ---- load row: 8 x float4 per lane, coalesced, streaming ----
    float v[32];
#pragma unroll
    for (int j = 0; j < 8; j++) {
        float4 t = __ldcs(reinterpret_cast<const float4*>(zr + j * 128 + lane * 4));
        v[4 * j + 0] = t.x;
        v[4 * j + 1] = t.y;
        v[4 * j + 2] = t.z;
        v[4 * j + 3] = t.w;
    }

    // ---- row max: register tree (ILP) + single-instruction int redux ----
    float m = v[0];
#pragma unroll
    for (int i = 1; i < 32; i++) m = fmaxf(m, v[i]);
    m = i2f_mono(__reduce_max_sync(0xffffffffu, f2i_mono(m)));

    float tau = m - 1.0f;

    // ---- per-lane binning of active values {z > tau0} into 3 registers ----
    float x0 = -CUDART_INF_F, x1 = -CUDART_INF_F, x2 = -CUDART_INF_F;
    int lc = 0;
#pragma unroll
    for (int i = 0; i < 32; i++) {
        if (v[i] > tau) {
            if (lc == 0)      x0 = v[i];
            else if (lc == 1) x1 = v[i];
            else if (lc == 2) x2 = v[i];
            lc++;
        }
    }
    const bool overflow = __ballot_sync(0xffffffffu, lc > 3) != 0u;

    // ---- Michelot fixed-point iterations ----
    if (!overflow) {
        // common case (~97%): all active values live in x0..x2 across the warp
#pragma unroll 1
        for (int it = 0; it < 40; it++) {
            bool a0 = x0 > tau, a1 = x1 > tau, a2 = x2 > tau;
            int k = __popc(__ballot_sync(0xffffffffu, a0))
                  + __popc(__ballot_sync(0xffffffffu, a1))
                  + __popc(__ballot_sync(0xffffffffu, a2));   // k >= 1 always
            float s = (a0 ? x0 : 0.0f) + (a1 ? x1 : 0.0f) + (a2 ? x2 : 0.0f);
            s = warp_sum(s);
            float nt = (s - 1.0f) / (float)k;
            if (nt == tau) break;   // exact fixed point = sparsemax threshold
            tau = nt;
        }
    } else {
        // rare fallback: iterate over the full register-resident row
#pragma unroll 1
        for (int it = 0; it < 64; it++) {
            float s = 0.0f, kk = 0.0f;
#pragma unroll
            for (int i = 0; i < 32; i++) {
                bool a = v[i] > tau;
                s  += a ? v[i] : 0.0f;
                kk += a ? 1.0f : 0.0f;
            }
            s  = warp_sum(s);
            kk = warp_sum(kk);
            float nt = (s - 1.0f) / kk;
            if (nt == tau) break;
            tau = nt;
        }
    }

    // ---- write p = relu(z - tau), coalesced float4 streaming stores ----
#pragma unroll
    for (int j = 0; j < 8; j++) {
        float4 t;
        t.x = fmaxf(v[4 * j + 0] - tau, 0.0f);
        t.y = fmaxf(v[4 * j + 1] - tau, 0.0f);
        t.z = fmaxf(v[4 * j + 2] - tau, 0.0f);
        t.w = fmaxf(v[4 * j + 3] - tau, 0.0f);
        __stcs(reinterpret_cast<float4*>(pr + j * 128 + lane * 4), t);
    }
}

extern "C" void kernel_launch(void* const* d_in, const int* in_sizes, int n_in,
                              void* d_out, int out_size) {
    const float* z = (const float*)d_in[0];
    float* p = (float*)d_out;
    const int rows = in_sizes[0] / D;                  // 32768
    const int grid = (rows + WPB - 1) / WPB;           // 4096
    sparsemax_kernel<<<grid, TPB>>>(z, p, rows);
}